// round 1
// baseline (speedup 1.0000x reference)
#include <cuda_runtime.h>
#include <math.h>

#define MAXB   4
#define MAXN   16384
#define MAXG   32
#define MAXBLK 128

#ifndef M_PI
#define M_PI 3.14159265358979323846
#endif

// ---------------- device scratch (no allocations allowed) ----------------
__device__ int                  g_lab[MAXB * MAXN];
__device__ float                g_mg[MAXB * MAXN * 5];
__device__ unsigned long long   g_best[MAXB * MAXG];
__device__ double               g_part[MAXB * MAXBLK * 3];

// ---------------- helpers ----------------
__device__ __forceinline__ float jrem180(float x) {
    // jnp.remainder(x, 180): result in [0, 180)
    float r = fmodf(x, 180.0f);
    if (r < 0.0f) r += 180.0f;
    return r;
}

__device__ __forceinline__ float lsig(float x) {
    // numerically stable log(sigmoid(x))
    return (x >= 0.0f) ? -log1pf(expf(-x)) : (x - log1pf(expf(x)));
}

// Exact intersection area of two convex CCW quads (double precision).
// Mirrors the reference algorithm: corner-inside tests (eps -1e-6),
// edge-edge intersections (den eps 1e-10), centroid angular sort, shoelace.
__device__ double quad_inter(const double* axp, const double* ayp,
                             const double* bxp, const double* byp)
{
    double px[24], py[24];
    int n = 0;

    // corners of A inside B
    #pragma unroll
    for (int i = 0; i < 4; i++) {
        bool ok = true;
        #pragma unroll
        for (int j = 0; j < 4; j++) {
            int j1 = (j + 1) & 3;
            double ex = bxp[j1] - bxp[j], ey = byp[j1] - byp[j];
            double dx = axp[i] - bxp[j], dy = ayp[i] - byp[j];
            if (ex * dy - ey * dx < -1e-6) ok = false;
        }
        if (ok) { px[n] = axp[i]; py[n] = ayp[i]; n++; }
    }
    // corners of B inside A
    #pragma unroll
    for (int i = 0; i < 4; i++) {
        bool ok = true;
        #pragma unroll
        for (int j = 0; j < 4; j++) {
            int j1 = (j + 1) & 3;
            double ex = axp[j1] - axp[j], ey = ayp[j1] - ayp[j];
            double dx = bxp[i] - axp[j], dy = byp[i] - ayp[j];
            if (ex * dy - ey * dx < -1e-6) ok = false;
        }
        if (ok) { px[n] = bxp[i]; py[n] = byp[i]; n++; }
    }
    // edge-edge intersections
    #pragma unroll
    for (int i = 0; i < 4; i++) {
        double a0x = axp[i], a0y = ayp[i];
        double rx = axp[(i + 1) & 3] - a0x, ry = ayp[(i + 1) & 3] - a0y;
        #pragma unroll
        for (int j = 0; j < 4; j++) {
            double c0x = bxp[j], c0y = byp[j];
            double ux = bxp[(j + 1) & 3] - c0x, uy = byp[(j + 1) & 3] - c0y;
            double den = rx * uy - ry * ux;
            if (fabs(den) > 1e-10) {
                double qx = c0x - a0x, qy = c0y - a0y;
                double tt = (qx * uy - qy * ux) / den;
                double ss = (qx * ry - qy * rx) / den;
                if (tt >= 0.0 && tt <= 1.0 && ss >= 0.0 && ss <= 1.0) {
                    px[n] = a0x + tt * rx;
                    py[n] = a0y + tt * ry;
                    n++;
                }
            }
        }
    }

    if (n < 3) return 0.0;

    double cx = 0.0, cy = 0.0;
    for (int k = 0; k < n; k++) { cx += px[k]; cy += py[k]; }
    cx /= n; cy /= n;

    float ang[24];
    for (int k = 0; k < n; k++)
        ang[k] = atan2f((float)(py[k] - cy), (float)(px[k] - cx));

    // insertion sort by angle
    for (int k = 1; k < n; k++) {
        float a = ang[k]; double X = px[k], Y = py[k];
        int m = k - 1;
        while (m >= 0 && ang[m] > a) {
            ang[m + 1] = ang[m]; px[m + 1] = px[m]; py[m + 1] = py[m];
            m--;
        }
        ang[m + 1] = a; px[m + 1] = X; py[m + 1] = Y;
    }

    double s = 0.0;
    for (int k = 0; k < n; k++) {
        int k1 = (k + 1 == n) ? 0 : k + 1;
        s += px[k] * py[k1] - px[k1] * py[k];
    }
    return 0.5 * fabs(s);
}

// ---------------- kernels ----------------
__global__ void init_kernel() {
    int t = blockIdx.x * blockDim.x + threadIdx.x;
    if (t < MAXB * MAXG) g_best[t] = 0ULL;
}

__global__ void assign_kernel(const float* __restrict__ anchors,
                              const float* __restrict__ gt_boxes,
                              const int*   __restrict__ gt_labels,
                              int N, int G)
{
    int b = blockIdx.y;
    int i = blockIdx.x * blockDim.x + threadIdx.x;
    int t = threadIdx.x;

    __shared__ double sgx[MAXG][4], sgy[MAXG][4];
    __shared__ float  sgb[MAXG][5];
    __shared__ float  sg_sz[MAXG];
    __shared__ double sg_area[MAXG];
    __shared__ int    s_gl[MAXG];
    __shared__ unsigned long long s_best[MAXG];

    if (t < G) {
        const float* gb = gt_boxes + (size_t)(b * G + t) * 5;
        float cxg = gb[0], cyg = gb[1], w = gb[2], h = gb[3], th = gb[4];
        #pragma unroll
        for (int k = 0; k < 5; k++) sgb[t][k] = gb[k];
        sg_sz[t]   = fmaxf(w, h);
        sg_area[t] = (double)w * (double)h;
        s_gl[t]    = gt_labels[b * G + t];
        double r = (double)th * (M_PI / 180.0);
        double c = cos(r), s = sin(r);
        double lx[4] = {-0.5 * w,  0.5 * w, 0.5 * w, -0.5 * w};
        double ly[4] = {-0.5 * h, -0.5 * h, 0.5 * h,  0.5 * h};
        #pragma unroll
        for (int k = 0; k < 4; k++) {
            sgx[t][k] = (double)cxg + lx[k] * c - ly[k] * s;
            sgy[t][k] = (double)cyg + lx[k] * s + ly[k] * c;
        }
        s_best[t] = 0ULL;
    }
    __syncthreads();

    if (i < N) {
        const float* ab = anchors + (size_t)i * 5;
        float ax = ab[0], ay = ab[1], aw = ab[2], ah = ab[3], ath = ab[4];
        float a_sz = fmaxf(aw, ah);
        double a_area = (double)aw * (double)ah;

        double acx[4], acy[4];
        {
            double r = (double)ath * (M_PI / 180.0);
            double c = cos(r), s = sin(r);
            double lx[4] = {-0.5 * aw,  0.5 * aw, 0.5 * aw, -0.5 * aw};
            double ly[4] = {-0.5 * ah, -0.5 * ah, 0.5 * ah,  0.5 * ah};
            #pragma unroll
            for (int k = 0; k < 4; k++) {
                acx[k] = (double)ax + lx[k] * c - ly[k] * s;
                acy[k] = (double)ay + lx[k] * s + ly[k] * c;
            }
        }

        float best_iou = 0.0f;
        int   best_j   = 0;
        for (int j = 0; j < G; j++) {
            float dx = ax - sgb[j][0];
            float dy = ay - sgb[j][1];
            float gate = (a_sz + sg_sz[j]) * 0.7f;  // fp32, like reference
            if (sqrtf(dx * dx + dy * dy) < gate) {
                double inter = quad_inter(acx, acy, sgx[j], sgy[j]);
                double iou_d = inter / (a_area + sg_area[j] - inter + 1e-8);
                float iou = (float)iou_d;
                if (iou > best_iou) { best_iou = iou; best_j = j; }
                if (iou > 0.0f) {
                    unsigned long long key =
                        ((unsigned long long)__float_as_uint(iou) << 32)
                        | (unsigned long long)(0xFFFFFFFFu - (unsigned)i);
                    atomicMax(&s_best[j], key);
                }
            }
        }

        int lab;
        if (best_iou >= 0.5f) {
            lab = s_gl[best_j] + 1;
            #pragma unroll
            for (int k = 0; k < 5; k++)
                g_mg[(size_t)(b * MAXN + i) * 5 + k] = sgb[best_j][k];
        } else {
            lab = (best_iou < 0.4f) ? 0 : -1;
        }
        g_lab[b * MAXN + i] = lab;
    }
    __syncthreads();

    if (t < G && s_best[t] != 0ULL)
        atomicMax(&g_best[b * MAXG + t], s_best[t]);
}

// Sequential low-quality force match, replicating the reference's G-loop
// order dependence. One thread per image.
__global__ void force_kernel(const float* __restrict__ gt_boxes,
                             const int*   __restrict__ gt_labels,
                             int N, int G)
{
    int b = blockIdx.x;
    if (threadIdx.x != 0) return;
    for (int j = 0; j < G; j++) {
        unsigned long long key = g_best[b * MAXG + j];
        if ((key >> 32) != 0ULL) {  // has[j]: max iou over anchors > 0
            int bi = (int)(0xFFFFFFFFu - (unsigned)(key & 0xFFFFFFFFu));
            int gl = gt_labels[b * G + j] + 1;
            if (g_lab[b * MAXN + bi] != gl) {
                g_lab[b * MAXN + bi] = gl;
                #pragma unroll
                for (int k = 0; k < 5; k++)
                    g_mg[(size_t)(b * MAXN + bi) * 5 + k] =
                        gt_boxes[(size_t)(b * G + j) * 5 + k];
            }
        }
    }
}

__global__ void loss_kernel(const float* __restrict__ logits,
                            const float* __restrict__ box_reg,
                            const float* __restrict__ anchors,
                            int N, int C)
{
    int b = blockIdx.y;
    int i = blockIdx.x * blockDim.x + threadIdx.x;
    int t = threadIdx.x;

    double fl_sum = 0.0, reg_sum = 0.0, np = 0.0;

    if (i < N) {
        int lab = g_lab[b * MAXN + i];
        bool valid = lab >= 0;
        bool pos   = lab > 0;

        if (valid) {
            const float* lp = logits + ((size_t)b * N + i) * (size_t)C;
            int tc = lab - 1;
            float fl = 0.0f;
            for (int c = 0; c < C; c++) {
                float x = lp[c];
                bool tt = pos && (c == tc);
                float p = 1.0f / (1.0f + expf(-x));
                float p_t     = tt ? p      : 1.0f - p;
                float alpha_t = tt ? 0.25f  : 0.75f;
                float bce = -(tt ? lsig(x) : lsig(-x));
                float om = 1.0f - p_t;
                fl += alpha_t * om * om * bce;
            }
            fl_sum = (double)fl;
        }

        if (pos) {
            np = 1.0;
            const float* ab = anchors + (size_t)i * 5;
            const float* mg = &g_mg[(size_t)(b * MAXN + i) * 5];
            const float* br = box_reg + ((size_t)b * N + i) * 5;

            float dlt[5];
            dlt[0] = (mg[0] - ab[0]) / ab[2];
            dlt[1] = (mg[1] - ab[1]) / ab[3];
            dlt[2] = logf(mg[2] / ab[2]);
            dlt[3] = logf(mg[3] / ab[3]);
            dlt[4] = jrem180(mg[4] - ab[4] + 90.0f) - 90.0f;

            float l = 0.0f;
            #pragma unroll
            for (int k = 0; k < 4; k++) {
                float d = fabsf(br[k] - dlt[k]);
                l += (d < 1.0f) ? 0.5f * d * d : d - 0.5f;
            }
            float da = fabsf(jrem180(br[4] - dlt[4] + 90.0f) - 90.0f);
            l += (da < 1.0f) ? 0.5f * da * da : da - 0.5f;
            reg_sum = (double)l;
        }
    }

    __shared__ double sf[256], sr[256], sn[256];
    sf[t] = fl_sum; sr[t] = reg_sum; sn[t] = np;
    __syncthreads();
    for (int s = 128; s > 0; s >>= 1) {
        if (t < s) { sf[t] += sf[t + s]; sr[t] += sr[t + s]; sn[t] += sn[t + s]; }
        __syncthreads();
    }
    if (t == 0) {
        size_t o = (size_t)(b * MAXBLK + blockIdx.x) * 3;
        g_part[o + 0] = sf[0];
        g_part[o + 1] = sr[0];
        g_part[o + 2] = sn[0];
    }
}

__global__ void final_kernel(float* __restrict__ out, int B, int nblk)
{
    if (threadIdx.x != 0 || blockIdx.x != 0) return;
    double cls_m = 0.0, reg_m = 0.0;
    for (int b = 0; b < B; b++) {
        double f = 0.0, r = 0.0, n = 0.0;
        for (int k = 0; k < nblk; k++) {
            size_t o = (size_t)(b * MAXBLK + k) * 3;
            f += g_part[o + 0];
            r += g_part[o + 1];
            n += g_part[o + 2];
        }
        double npos = (n < 1.0) ? 1.0 : n;
        cls_m += f / npos;
        reg_m += r / npos;
    }
    cls_m /= (double)B;
    reg_m /= (double)B;
    out[0] = (float)(cls_m + reg_m);
    out[1] = (float)cls_m;
    out[2] = (float)reg_m;
}

// ---------------- launch ----------------
extern "C" void kernel_launch(void* const* d_in, const int* in_sizes, int n_in,
                              void* d_out, int out_size)
{
    const float* logits  = (const float*)d_in[0];
    const float* breg    = (const float*)d_in[1];
    const float* anchors = (const float*)d_in[2];
    const float* gtb     = (const float*)d_in[3];
    const int*   gtl     = (const int*)d_in[4];

    int N = in_sizes[2] / 5;              // anchors: (N,5)
    int B = in_sizes[1] / (5 * N);        // box_reg: (B,N,5)
    int C = in_sizes[0] / (B * N);        // logits : (B,N,C)
    int G = in_sizes[4] / B;              // labels : (B,G)

    init_kernel<<<1, 256>>>();

    dim3 ag((N + 127) / 128, B);
    assign_kernel<<<ag, 128>>>(anchors, gtb, gtl, N, G);

    force_kernel<<<B, 1>>>(gtb, gtl, N, G);

    int nblk = (N + 255) / 256;
    dim3 lg(nblk, B);
    loss_kernel<<<lg, 256>>>(logits, breg, anchors, N, C);

    final_kernel<<<1, 1>>>((float*)d_out, B, nblk);
}

// round 2
// speedup vs baseline: 10.7798x; 10.7798x over previous
#include <cuda_runtime.h>
#include <math.h>

#define MAXB   4
#define MAXN   16384
#define MAXG   32
#define MAXBLK 256
#define ABLK   128

#ifndef M_PI
#define M_PI 3.14159265358979323846
#endif

// ---------------- device scratch (no allocations allowed) ----------------
__device__ int                  g_lab[MAXB * MAXN];
__device__ float                g_mg[MAXB * MAXN * 5];
__device__ unsigned long long   g_best[MAXB * MAXG];
__device__ double               g_part[MAXB * MAXBLK * 3];

// ---------------- helpers ----------------
__device__ __forceinline__ float jrem180(float x) {
    float r = fmodf(x, 180.0f);
    if (r < 0.0f) r += 180.0f;
    return r;
}

__device__ __forceinline__ float lsig(float x) {
    return (x >= 0.0f) ? -log1pf(expf(-x)) : (x - log1pf(expf(x)));
}

// Exact intersection area of two convex CCW quads, fp32, mirroring the
// reference algorithm: corner-inside tests (eps -1e-6), edge-edge
// intersections (den eps 1e-10), centroid angular sort, shoelace.
__device__ float quad_inter_f(const float* axp, const float* ayp,
                              const float* bxp, const float* byp)
{
    float px[24], py[24];
    int n = 0;

    #pragma unroll
    for (int i = 0; i < 4; i++) {
        bool ok = true;
        #pragma unroll
        for (int j = 0; j < 4; j++) {
            int j1 = (j + 1) & 3;
            float ex = bxp[j1] - bxp[j], ey = byp[j1] - byp[j];
            float dx = axp[i] - bxp[j], dy = ayp[i] - byp[j];
            if (ex * dy - ey * dx < -1e-6f) ok = false;
        }
        if (ok) { px[n] = axp[i]; py[n] = ayp[i]; n++; }
    }
    #pragma unroll
    for (int i = 0; i < 4; i++) {
        bool ok = true;
        #pragma unroll
        for (int j = 0; j < 4; j++) {
            int j1 = (j + 1) & 3;
            float ex = axp[j1] - axp[j], ey = ayp[j1] - ayp[j];
            float dx = bxp[i] - axp[j], dy = byp[i] - ayp[j];
            if (ex * dy - ey * dx < -1e-6f) ok = false;
        }
        if (ok) { px[n] = bxp[i]; py[n] = byp[i]; n++; }
    }
    #pragma unroll
    for (int i = 0; i < 4; i++) {
        float a0x = axp[i], a0y = ayp[i];
        float rx = axp[(i + 1) & 3] - a0x, ry = ayp[(i + 1) & 3] - a0y;
        #pragma unroll
        for (int j = 0; j < 4; j++) {
            float c0x = bxp[j], c0y = byp[j];
            float ux = bxp[(j + 1) & 3] - c0x, uy = byp[(j + 1) & 3] - c0y;
            float den = rx * uy - ry * ux;
            if (fabsf(den) > 1e-10f) {
                float qx = c0x - a0x, qy = c0y - a0y;
                float tt = (qx * uy - qy * ux) / den;
                float ss = (qx * ry - qy * rx) / den;
                if (tt >= 0.0f && tt <= 1.0f && ss >= 0.0f && ss <= 1.0f) {
                    px[n] = a0x + tt * rx;
                    py[n] = a0y + tt * ry;
                    n++;
                }
            }
        }
    }

    if (n < 3) return 0.0f;

    float cx = 0.0f, cy = 0.0f;
    for (int k = 0; k < n; k++) { cx += px[k]; cy += py[k]; }
    cx /= (float)n; cy /= (float)n;

    float ang[24];
    for (int k = 0; k < n; k++)
        ang[k] = atan2f(py[k] - cy, px[k] - cx);

    for (int k = 1; k < n; k++) {
        float a = ang[k], X = px[k], Y = py[k];
        int m = k - 1;
        while (m >= 0 && ang[m] > a) {
            ang[m + 1] = ang[m]; px[m + 1] = px[m]; py[m + 1] = py[m];
            m--;
        }
        ang[m + 1] = a; px[m + 1] = X; py[m + 1] = Y;
    }

    float s = 0.0f;
    for (int k = 0; k < n; k++) {
        int k1 = (k + 1 == n) ? 0 : k + 1;
        s += px[k] * py[k1] - px[k1] * py[k];
    }
    return 0.5f * fabsf(s);
}

__device__ __forceinline__ void make_corners_f(float cx, float cy, float w,
                                               float h, float th,
                                               float* X, float* Y)
{
    float r = th * (float)(M_PI / 180.0);
    float c = cosf(r), s = sinf(r);
    float lx[4] = {-0.5f * w,  0.5f * w, 0.5f * w, -0.5f * w};
    float ly[4] = {-0.5f * h, -0.5f * h, 0.5f * h,  0.5f * h};
    #pragma unroll
    for (int k = 0; k < 4; k++) {
        X[k] = cx + lx[k] * c - ly[k] * s;
        Y[k] = cy + lx[k] * s + ly[k] * c;
    }
}

// ---------------- kernels ----------------
__global__ void init_kernel() {
    int t = blockIdx.x * blockDim.x + threadIdx.x;
    if (t < MAXB * MAXG) g_best[t] = 0ULL;
}

__global__ void assign_kernel(const float* __restrict__ anchors,
                              const float* __restrict__ gt_boxes,
                              const int*   __restrict__ gt_labels,
                              int N, int G)
{
    int b  = blockIdx.y;
    int i0 = blockIdx.x * ABLK;
    int t  = threadIdx.x;
    int i  = i0 + t;

    __shared__ float sgx[MAXG][4], sgy[MAXG][4];
    __shared__ float sgb[MAXG][5];
    __shared__ float sg_sz[MAXG];
    __shared__ float sg_area[MAXG];
    __shared__ int   s_gl[MAXG];
    __shared__ unsigned long long s_best[MAXG];
    __shared__ float s_anc[ABLK][5];
    __shared__ float s_iou[ABLK][MAXG];
    __shared__ int   s_q[ABLK * 16];
    __shared__ int   s_qn;

    if (t == 0) s_qn = 0;
    if (t < G) {
        const float* gb = gt_boxes + (size_t)(b * G + t) * 5;
        float w = gb[2], h = gb[3];
        #pragma unroll
        for (int k = 0; k < 5; k++) sgb[t][k] = gb[k];
        sg_sz[t]   = fmaxf(w, h);
        sg_area[t] = w * h;
        s_gl[t]    = gt_labels[b * G + t];
        make_corners_f(gb[0], gb[1], w, h, gb[4], sgx[t], sgy[t]);
        s_best[t] = 0ULL;
    }
    if (i < N) {
        const float* ab = anchors + (size_t)i * 5;
        #pragma unroll
        for (int k = 0; k < 5; k++) s_anc[t][k] = ab[k];
    }
    for (int j = 0; j < MAXG; j++) s_iou[t][j] = 0.0f;
    __syncthreads();

    // phase 1: gate, build pair queue
    if (i < N) {
        float ax = s_anc[t][0], ay = s_anc[t][1];
        float a_sz = fmaxf(s_anc[t][2], s_anc[t][3]);
        for (int j = 0; j < G; j++) {
            float dx = ax - sgb[j][0];
            float dy = ay - sgb[j][1];
            float gate = (a_sz + sg_sz[j]) * 0.7f;
            if (sqrtf(dx * dx + dy * dy) < gate) {
                int p = atomicAdd(&s_qn, 1);
                s_q[p] = (t << 5) | j;
            }
        }
    }
    __syncthreads();

    // phase 2: all threads drain the queue (load-balanced)
    int qn = s_qn;
    for (int q = t; q < qn; q += ABLK) {
        int e  = s_q[q];
        int li = e >> 5;
        int j  = e & 31;
        float acx[4], acy[4];
        make_corners_f(s_anc[li][0], s_anc[li][1], s_anc[li][2],
                       s_anc[li][3], s_anc[li][4], acx, acy);
        float a_area = s_anc[li][2] * s_anc[li][3];
        float inter = quad_inter_f(acx, acy, sgx[j], sgy[j]);
        s_iou[li][j] = inter / (a_area + sg_area[j] - inter + 1e-8f);
    }
    __syncthreads();

    // phase 3: per-anchor argmax, thresholds, per-GT best via packed atomicMax
    if (i < N) {
        float best_iou = 0.0f;
        int   best_j   = 0;
        for (int j = 0; j < G; j++) {
            float iou = s_iou[t][j];
            if (iou > best_iou) { best_iou = iou; best_j = j; }
            if (iou > 0.0f) {
                unsigned long long key =
                    ((unsigned long long)__float_as_uint(iou) << 32)
                    | (unsigned long long)(0xFFFFFFFFu - (unsigned)i);
                atomicMax(&s_best[j], key);
            }
        }
        int lab;
        if (best_iou >= 0.5f) {
            lab = s_gl[best_j] + 1;
            #pragma unroll
            for (int k = 0; k < 5; k++)
                g_mg[(size_t)(b * MAXN + i) * 5 + k] = sgb[best_j][k];
        } else {
            lab = (best_iou < 0.4f) ? 0 : -1;
        }
        g_lab[b * MAXN + i] = lab;
    }
    __syncthreads();

    if (t < G && s_best[t] != 0ULL)
        atomicMax(&g_best[b * MAXG + t], s_best[t]);
}

// Sequential low-quality force match (reference's order-dependent G-loop).
__global__ void force_kernel(const float* __restrict__ gt_boxes,
                             const int*   __restrict__ gt_labels,
                             int N, int G)
{
    int b = blockIdx.x;
    if (threadIdx.x != 0) return;
    for (int j = 0; j < G; j++) {
        unsigned long long key = g_best[b * MAXG + j];
        if ((key >> 32) != 0ULL) {
            int bi = (int)(0xFFFFFFFFu - (unsigned)(key & 0xFFFFFFFFu));
            int gl = gt_labels[b * G + j] + 1;
            if (g_lab[b * MAXN + bi] != gl) {
                g_lab[b * MAXN + bi] = gl;
                #pragma unroll
                for (int k = 0; k < 5; k++)
                    g_mg[(size_t)(b * MAXN + bi) * 5 + k] =
                        gt_boxes[(size_t)(b * G + j) * 5 + k];
            }
        }
    }
}

__global__ void loss_kernel(const float* __restrict__ logits,
                            const float* __restrict__ box_reg,
                            const float* __restrict__ anchors,
                            int N, int C)
{
    int b = blockIdx.y;
    int i = blockIdx.x * blockDim.x + threadIdx.x;
    int t = threadIdx.x;

    double fl_sum = 0.0, reg_sum = 0.0, np = 0.0;

    if (i < N) {
        int lab = g_lab[b * MAXN + i];
        bool valid = lab >= 0;
        bool pos   = lab > 0;

        if (valid) {
            const float* lp = logits + ((size_t)b * N + i) * (size_t)C;
            int tc = lab - 1;
            float fl = 0.0f;
            for (int c = 0; c < C; c++) {
                float x = __ldg(lp + c);
                bool tt = pos && (c == tc);
                float p = 1.0f / (1.0f + expf(-x));
                float p_t     = tt ? p      : 1.0f - p;
                float alpha_t = tt ? 0.25f  : 0.75f;
                float bce = -(tt ? lsig(x) : lsig(-x));
                float om = 1.0f - p_t;
                fl += alpha_t * om * om * bce;
            }
            fl_sum = (double)fl;
        }

        if (pos) {
            np = 1.0;
            const float* ab = anchors + (size_t)i * 5;
            const float* mg = &g_mg[(size_t)(b * MAXN + i) * 5];
            const float* br = box_reg + ((size_t)b * N + i) * 5;

            float dlt[5];
            dlt[0] = (mg[0] - ab[0]) / ab[2];
            dlt[1] = (mg[1] - ab[1]) / ab[3];
            dlt[2] = logf(mg[2] / ab[2]);
            dlt[3] = logf(mg[3] / ab[3]);
            dlt[4] = jrem180(mg[4] - ab[4] + 90.0f) - 90.0f;

            float l = 0.0f;
            #pragma unroll
            for (int k = 0; k < 4; k++) {
                float d = fabsf(br[k] - dlt[k]);
                l += (d < 1.0f) ? 0.5f * d * d : d - 0.5f;
            }
            float da = fabsf(jrem180(br[4] - dlt[4] + 90.0f) - 90.0f);
            l += (da < 1.0f) ? 0.5f * da * da : da - 0.5f;
            reg_sum = (double)l;
        }
    }

    __shared__ double sf[128], sr[128], sn[128];
    sf[t] = fl_sum; sr[t] = reg_sum; sn[t] = np;
    __syncthreads();
    for (int s = 64; s > 0; s >>= 1) {
        if (t < s) { sf[t] += sf[t + s]; sr[t] += sr[t + s]; sn[t] += sn[t + s]; }
        __syncthreads();
    }
    if (t == 0) {
        size_t o = (size_t)(b * MAXBLK + blockIdx.x) * 3;
        g_part[o + 0] = sf[0];
        g_part[o + 1] = sr[0];
        g_part[o + 2] = sn[0];
    }
}

__global__ void final_kernel(float* __restrict__ out, int B, int nblk)
{
    if (threadIdx.x != 0 || blockIdx.x != 0) return;
    double cls_m = 0.0, reg_m = 0.0;
    for (int b = 0; b < B; b++) {
        double f = 0.0, r = 0.0, n = 0.0;
        for (int k = 0; k < nblk; k++) {
            size_t o = (size_t)(b * MAXBLK + k) * 3;
            f += g_part[o + 0];
            r += g_part[o + 1];
            n += g_part[o + 2];
        }
        double npos = (n < 1.0) ? 1.0 : n;
        cls_m += f / npos;
        reg_m += r / npos;
    }
    cls_m /= (double)B;
    reg_m /= (double)B;
    out[0] = (float)(cls_m + reg_m);
    out[1] = (float)cls_m;
    out[2] = (float)reg_m;
}

// ---------------- launch ----------------
extern "C" void kernel_launch(void* const* d_in, const int* in_sizes, int n_in,
                              void* d_out, int out_size)
{
    const float* logits  = (const float*)d_in[0];
    const float* breg    = (const float*)d_in[1];
    const float* anchors = (const float*)d_in[2];
    const float* gtb     = (const float*)d_in[3];
    const int*   gtl     = (const int*)d_in[4];

    int N = in_sizes[2] / 5;              // anchors: (N,5)
    int B = in_sizes[1] / (5 * N);        // box_reg: (B,N,5)
    int C = in_sizes[0] / (B * N);        // logits : (B,N,C)
    int G = in_sizes[4] / B;              // labels : (B,G)

    init_kernel<<<1, 256>>>();

    dim3 ag((N + ABLK - 1) / ABLK, B);
    assign_kernel<<<ag, ABLK>>>(anchors, gtb, gtl, N, G);

    force_kernel<<<B, 1>>>(gtb, gtl, N, G);

    int nblk = (N + 127) / 128;
    dim3 lg(nblk, B);
    loss_kernel<<<lg, 128>>>(logits, breg, anchors, N, C);

    final_kernel<<<1, 1>>>((float*)d_out, B, nblk);
}

// round 3
// speedup vs baseline: 17.8272x; 1.6538x over previous
#include <cuda_runtime.h>
#include <math.h>

#define MAXB   4
#define MAXN   16384
#define MAXG   32
#define MAXBLK 256
#define ABLK   128

#ifndef M_PI
#define M_PI 3.14159265358979323846
#endif

// ---------------- device scratch (no allocations allowed) ----------------
__device__ int                  g_lab[MAXB * MAXN];
__device__ float                g_mg[MAXB * MAXN * 5];
__device__ unsigned long long   g_best[MAXB * MAXG];   // zero-init; force_kernel re-zeros
__device__ double               g_part[MAXB * MAXBLK * 3];

// ---------------- helpers ----------------
__device__ __forceinline__ float jrem180(float x) {
    float r = fmodf(x, 180.0f);
    if (r < 0.0f) r += 180.0f;
    return r;
}

// Sutherland–Hodgman: clip convex CCW quad A by convex CCW quad B, shoelace area.
__device__ float quad_clip_area(const float* axp, const float* ayp,
                                const float* bxp, const float* byp)
{
    float Px[8], Py[8], Qx[8], Qy[8];
    int n = 4;
    #pragma unroll
    for (int k = 0; k < 4; k++) { Px[k] = axp[k]; Py[k] = ayp[k]; }

    #pragma unroll
    for (int j = 0; j < 4; j++) {
        float cx0 = bxp[j], cy0 = byp[j];
        int j1 = (j + 1) & 3;
        float ex = bxp[j1] - cx0, ey = byp[j1] - cy0;
        int m = 0;
        for (int k = 0; k < n; k++) {
            int k1 = (k + 1 == n) ? 0 : k + 1;
            float x0 = Px[k],  y0 = Py[k];
            float x1 = Px[k1], y1 = Py[k1];
            float d0 = ex * (y0 - cy0) - ey * (x0 - cx0);
            float d1 = ex * (y1 - cy0) - ey * (x1 - cx0);
            bool in0 = d0 >= 0.0f, in1 = d1 >= 0.0f;
            if (in0) { Qx[m] = x0; Qy[m] = y0; m++; }
            if (in0 != in1) {
                float t = d0 / (d0 - d1);
                Qx[m] = x0 + t * (x1 - x0);
                Qy[m] = y0 + t * (y1 - y0);
                m++;
            }
        }
        n = m;
        if (n == 0) break;
        for (int k = 0; k < n; k++) { Px[k] = Qx[k]; Py[k] = Qy[k]; }
    }

    if (n < 3) return 0.0f;
    float s = 0.0f;
    for (int k = 0; k < n; k++) {
        int k1 = (k + 1 == n) ? 0 : k + 1;
        s += Px[k] * Py[k1] - Px[k1] * Py[k];
    }
    return 0.5f * fabsf(s);
}

__device__ __forceinline__ void make_corners_f(float cx, float cy, float w,
                                               float h, float th,
                                               float* X, float* Y)
{
    float r = th * (float)(M_PI / 180.0);
    float c, s;
    __sincosf(r, &s, &c);
    // __sincosf is fast-math; use precise versions to stay near reference:
    c = cosf(r); s = sinf(r);
    float lx[4] = {-0.5f * w,  0.5f * w, 0.5f * w, -0.5f * w};
    float ly[4] = {-0.5f * h, -0.5f * h, 0.5f * h,  0.5f * h};
    #pragma unroll
    for (int k = 0; k < 4; k++) {
        X[k] = cx + lx[k] * c - ly[k] * s;
        Y[k] = cy + lx[k] * s + ly[k] * c;
    }
}

// ---------------- kernels ----------------
__global__ void assign_kernel(const float* __restrict__ anchors,
                              const float* __restrict__ gt_boxes,
                              const int*   __restrict__ gt_labels,
                              int N, int G)
{
    int b  = blockIdx.y;
    int i0 = blockIdx.x * ABLK;
    int t  = threadIdx.x;
    int i  = i0 + t;

    __shared__ float sgx[MAXG][4], sgy[MAXG][4];
    __shared__ float sgb[MAXG][5];
    __shared__ float sg_sz[MAXG];
    __shared__ float sg_area[MAXG];
    __shared__ int   s_gl[MAXG];
    __shared__ unsigned long long s_best[MAXG];
    __shared__ float s_anc[ABLK][5];
    __shared__ float s_acx[ABLK][4], s_acy[ABLK][4];
    __shared__ float s_iou[ABLK][MAXG];
    __shared__ int   s_q[ABLK * MAXG];
    __shared__ int   s_qn;

    if (t == 0) s_qn = 0;
    if (t < G) {
        const float* gb = gt_boxes + (size_t)(b * G + t) * 5;
        float w = gb[2], h = gb[3];
        #pragma unroll
        for (int k = 0; k < 5; k++) sgb[t][k] = gb[k];
        sg_sz[t]   = fmaxf(w, h);
        sg_area[t] = w * h;
        s_gl[t]    = gt_labels[b * G + t];
        make_corners_f(gb[0], gb[1], w, h, gb[4], sgx[t], sgy[t]);
        s_best[t] = 0ULL;
    }
    if (i < N) {
        const float* ab = anchors + (size_t)i * 5;
        #pragma unroll
        for (int k = 0; k < 5; k++) s_anc[t][k] = ab[k];
        make_corners_f(ab[0], ab[1], ab[2], ab[3], ab[4], s_acx[t], s_acy[t]);
    }
    for (int j = 0; j < G; j++) s_iou[t][j] = 0.0f;
    __syncthreads();

    // phase 1: gate, build pair queue
    if (i < N) {
        float ax = s_anc[t][0], ay = s_anc[t][1];
        float a_sz = fmaxf(s_anc[t][2], s_anc[t][3]);
        for (int j = 0; j < G; j++) {
            float dx = ax - sgb[j][0];
            float dy = ay - sgb[j][1];
            float gate = (a_sz + sg_sz[j]) * 0.7f;
            if (sqrtf(dx * dx + dy * dy) < gate) {
                int p = atomicAdd(&s_qn, 1);
                s_q[p] = (t << 5) | j;
            }
        }
    }
    __syncthreads();

    // phase 2: all threads drain the queue (load-balanced)
    int qn = s_qn;
    for (int q = t; q < qn; q += ABLK) {
        int e  = s_q[q];
        int li = e >> 5;
        int j  = e & 31;
        float a_area = s_anc[li][2] * s_anc[li][3];
        float inter = quad_clip_area(s_acx[li], s_acy[li], sgx[j], sgy[j]);
        s_iou[li][j] = inter / (a_area + sg_area[j] - inter + 1e-8f);
    }
    __syncthreads();

    // phase 3: per-anchor argmax, thresholds, per-GT best via packed atomicMax
    if (i < N) {
        float best_iou = 0.0f;
        int   best_j   = 0;
        for (int j = 0; j < G; j++) {
            float iou = s_iou[t][j];
            if (iou > best_iou) { best_iou = iou; best_j = j; }
            if (iou > 0.0f) {
                unsigned long long key =
                    ((unsigned long long)__float_as_uint(iou) << 32)
                    | (unsigned long long)(0xFFFFFFFFu - (unsigned)i);
                atomicMax(&s_best[j], key);
            }
        }
        int lab;
        if (best_iou >= 0.5f) {
            lab = s_gl[best_j] + 1;
            #pragma unroll
            for (int k = 0; k < 5; k++)
                g_mg[(size_t)(b * MAXN + i) * 5 + k] = sgb[best_j][k];
        } else {
            lab = (best_iou < 0.4f) ? 0 : -1;
        }
        g_lab[b * MAXN + i] = lab;
    }
    __syncthreads();

    if (t < G && s_best[t] != 0ULL)
        atomicMax(&g_best[b * MAXG + t], s_best[t]);
}

// Sequential low-quality force match (reference's order-dependent G-loop).
// Also re-zeros g_best so the next graph replay starts clean.
__global__ void force_kernel(const float* __restrict__ gt_boxes,
                             const int*   __restrict__ gt_labels,
                             int N, int G)
{
    int b = blockIdx.x;
    if (threadIdx.x != 0) return;
    for (int j = 0; j < G; j++) {
        unsigned long long key = g_best[b * MAXG + j];
        g_best[b * MAXG + j] = 0ULL;
        if ((key >> 32) != 0ULL) {
            int bi = (int)(0xFFFFFFFFu - (unsigned)(key & 0xFFFFFFFFu));
            int gl = gt_labels[b * G + j] + 1;
            if (g_lab[b * MAXN + bi] != gl) {
                g_lab[b * MAXN + bi] = gl;
                #pragma unroll
                for (int k = 0; k < 5; k++)
                    g_mg[(size_t)(b * MAXN + bi) * 5 + k] =
                        gt_boxes[(size_t)(b * G + j) * 5 + k];
            }
        }
    }
}

__global__ void loss_kernel(const float* __restrict__ logits,
                            const float* __restrict__ box_reg,
                            const float* __restrict__ anchors,
                            int N, int C)
{
    int b = blockIdx.y;
    int i = blockIdx.x * blockDim.x + threadIdx.x;
    int t = threadIdx.x;

    double fl_sum = 0.0, reg_sum = 0.0, np = 0.0;

    if (i < N) {
        int lab = g_lab[b * MAXN + i];
        bool valid = lab >= 0;
        bool pos   = lab > 0;

        if (valid) {
            const float* lp = logits + ((size_t)b * N + i) * (size_t)C;
            int tc = lab - 1;
            float fl = 0.0f;
            for (int c = 0; c < C; c++) {
                float x = __ldg(lp + c);
                bool tt = pos && (c == tc);
                // e = exp(-x); denom = 1+e; L = log(denom) = -logsig(x)
                // logsig(-x) = logsig(x) - x = -L - x
                float e     = __expf(-x);
                float denom = 1.0f + e;
                float L     = __logf(denom);
                float inv   = __fdividef(1.0f, denom);  // p = sigmoid(x)
                float om    = tt ? e * inv : inv;       // 1 - p_t
                float alpha = tt ? 0.25f : 0.75f;
                float bce   = tt ? L : (L + x);
                fl += alpha * om * om * bce;
            }
            fl_sum = (double)fl;
        }

        if (pos) {
            np = 1.0;
            const float* ab = anchors + (size_t)i * 5;
            const float* mg = &g_mg[(size_t)(b * MAXN + i) * 5];
            const float* br = box_reg + ((size_t)b * N + i) * 5;

            float dlt[5];
            dlt[0] = (mg[0] - ab[0]) / ab[2];
            dlt[1] = (mg[1] - ab[1]) / ab[3];
            dlt[2] = logf(mg[2] / ab[2]);
            dlt[3] = logf(mg[3] / ab[3]);
            dlt[4] = jrem180(mg[4] - ab[4] + 90.0f) - 90.0f;

            float l = 0.0f;
            #pragma unroll
            for (int k = 0; k < 4; k++) {
                float d = fabsf(br[k] - dlt[k]);
                l += (d < 1.0f) ? 0.5f * d * d : d - 0.5f;
            }
            float da = fabsf(jrem180(br[4] - dlt[4] + 90.0f) - 90.0f);
            l += (da < 1.0f) ? 0.5f * da * da : da - 0.5f;
            reg_sum = (double)l;
        }
    }

    __shared__ double sf[128], sr[128], sn[128];
    sf[t] = fl_sum; sr[t] = reg_sum; sn[t] = np;
    __syncthreads();
    for (int s = 64; s > 0; s >>= 1) {
        if (t < s) { sf[t] += sf[t + s]; sr[t] += sr[t + s]; sn[t] += sn[t + s]; }
        __syncthreads();
    }
    if (t == 0) {
        size_t o = (size_t)(b * MAXBLK + blockIdx.x) * 3;
        g_part[o + 0] = sf[0];
        g_part[o + 1] = sr[0];
        g_part[o + 2] = sn[0];
    }
}

__global__ void final_kernel(float* __restrict__ out, int B, int nblk)
{
    // one block, 256 threads; parallel reduce per image then combine
    int t = threadIdx.x;
    __shared__ double sf[256], sr[256], sn[256];
    __shared__ double res[2][2];  // [b][cls,reg] partial means

    double cls_m = 0.0, reg_m = 0.0;
    for (int b = 0; b < B; b++) {
        double f = 0.0, r = 0.0, n = 0.0;
        for (int k = t; k < nblk; k += 256) {
            size_t o = (size_t)(b * MAXBLK + k) * 3;
            f += g_part[o + 0];
            r += g_part[o + 1];
            n += g_part[o + 2];
        }
        sf[t] = f; sr[t] = r; sn[t] = n;
        __syncthreads();
        for (int s = 128; s > 0; s >>= 1) {
            if (t < s) { sf[t] += sf[t + s]; sr[t] += sr[t + s]; sn[t] += sn[t + s]; }
            __syncthreads();
        }
        if (t == 0) {
            double npos = (sn[0] < 1.0) ? 1.0 : sn[0];
            res[b & 1][0] = sf[0] / npos;
            res[b & 1][1] = sr[0] / npos;
        }
        __syncthreads();
        if (t == 0) { cls_m += res[b & 1][0]; reg_m += res[b & 1][1]; }
    }
    if (t == 0) {
        cls_m /= (double)B;
        reg_m /= (double)B;
        out[0] = (float)(cls_m + reg_m);
        out[1] = (float)cls_m;
        out[2] = (float)reg_m;
    }
}

// ---------------- launch ----------------
extern "C" void kernel_launch(void* const* d_in, const int* in_sizes, int n_in,
                              void* d_out, int out_size)
{
    const float* logits  = (const float*)d_in[0];
    const float* breg    = (const float*)d_in[1];
    const float* anchors = (const float*)d_in[2];
    const float* gtb     = (const float*)d_in[3];
    const int*   gtl     = (const int*)d_in[4];

    int N = in_sizes[2] / 5;              // anchors: (N,5)
    int B = in_sizes[1] / (5 * N);        // box_reg: (B,N,5)
    int C = in_sizes[0] / (B * N);        // logits : (B,N,C)
    int G = in_sizes[4] / B;              // labels : (B,G)

    dim3 ag((N + ABLK - 1) / ABLK, B);
    assign_kernel<<<ag, ABLK>>>(anchors, gtb, gtl, N, G);

    force_kernel<<<B, 1>>>(gtb, gtl, N, G);

    int nblk = (N + 127) / 128;
    dim3 lg(nblk, B);
    loss_kernel<<<lg, 128>>>(logits, breg, anchors, N, C);

    final_kernel<<<1, 256>>>((float*)d_out, B, nblk);
}